// round 1
// baseline (speedup 1.0000x reference)
#include <cuda_runtime.h>
#include <cuda_bf16.h>
#include <math_constants.h>

// Problem constants (shapes fixed by the dataset)
#define CC      128      // channels
#define BATCH   64
#define HW      3136     // 56*56
#define NCH     8        // num_chunks
#define CHUNK_B (BATCH / NCH)       // 8 batches per chunk
#define CHUNK_SZ (CHUNK_B * HW)     // 25088 elements per chunk
#define NTOT    ((size_t)BATCH * HW)            // per-channel sample count 200704
#define TOTAL4  ((size_t)BATCH * CC * HW / 4)   // 6,422,528 float4s
#define HW4     (HW / 4)            // 784 float4 per image-plane

// Scratch (no cudaMalloc allowed)
__device__ float g_cmax[CC * NCH];
__device__ float g_cmin[CC * NCH];
__device__ float g_csum[CC * NCH];
__device__ float g_avg[CC];
__device__ float g_scale[CC];

__device__ __forceinline__ float qbf(float v) {
    return __bfloat162float(__float2bfloat16(v)); // round-to-nearest bf16, back to fp32
}

// ---------------------------------------------------------------------------
// Kernel 1: per (channel, chunk) max / min / sum of bf16-quantized x
// grid = CC*NCH = 1024 blocks, 256 threads
// ---------------------------------------------------------------------------
__global__ __launch_bounds__(256) void rbn_reduce(const float* __restrict__ x) {
    const int c = blockIdx.x >> 3;     // channel
    const int k = blockIdx.x & 7;      // chunk
    const int tid = threadIdx.x;

    float vmax = -CUDART_INF_F;
    float vmin =  CUDART_INF_F;
    float vsum = 0.0f;

    #pragma unroll
    for (int b = 0; b < CHUNK_B; ++b) {
        const size_t plane = ((size_t)(k * CHUNK_B + b) * CC + c) * HW;
        const float4* p = reinterpret_cast<const float4*>(x + plane);
        for (int i = tid; i < HW4; i += 256) {
            float4 v = __ldg(p + i);
            float a0 = qbf(v.x), a1 = qbf(v.y), a2 = qbf(v.z), a3 = qbf(v.w);
            vmax = fmaxf(vmax, fmaxf(fmaxf(a0, a1), fmaxf(a2, a3)));
            vmin = fminf(vmin, fminf(fminf(a0, a1), fminf(a2, a3)));
            vsum += (a0 + a1) + (a2 + a3);
        }
    }

    // block reduce: 8 warps
    __shared__ float smax[8], smin[8], ssum[8];
    const int lane = tid & 31, wid = tid >> 5;
    #pragma unroll
    for (int off = 16; off > 0; off >>= 1) {
        vmax = fmaxf(vmax, __shfl_xor_sync(0xffffffff, vmax, off));
        vmin = fminf(vmin, __shfl_xor_sync(0xffffffff, vmin, off));
        vsum += __shfl_xor_sync(0xffffffff, vsum, off);
    }
    if (lane == 0) { smax[wid] = vmax; smin[wid] = vmin; ssum[wid] = vsum; }
    __syncthreads();
    if (wid == 0) {
        vmax = (lane < 8) ? smax[lane] : -CUDART_INF_F;
        vmin = (lane < 8) ? smin[lane] :  CUDART_INF_F;
        vsum = (lane < 8) ? ssum[lane] : 0.0f;
        #pragma unroll
        for (int off = 4; off > 0; off >>= 1) {
            vmax = fmaxf(vmax, __shfl_xor_sync(0xffffffff, vmax, off));
            vmin = fminf(vmin, __shfl_xor_sync(0xffffffff, vmin, off));
            vsum += __shfl_xor_sync(0xffffffff, vsum, off);
        }
        if (lane == 0) {
            g_cmax[c * NCH + k] = vmax;
            g_cmin[c * NCH + k] = vmin;
            g_csum[c * NCH + k] = vsum;
        }
    }
}

// ---------------------------------------------------------------------------
// Kernel 2: per-channel combine, exactly following reference _q() chain
// 1 block, 128 threads (one per channel)
// ---------------------------------------------------------------------------
__global__ void rbn_combine() {
    const int c = threadIdx.x;
    if (c >= CC) return;
    float sm = 0.f, sn = 0.f, st = 0.f;
    #pragma unroll
    for (int k = 0; k < NCH; ++k) {
        sm += g_cmax[c * NCH + k];
        sn += g_cmin[c * NCH + k];
        st += g_csum[c * NCH + k];
    }
    float sum_max = qbf(sm);
    float sum_min = qbf(sn);
    float avg_max = qbf(sum_max / (float)NCH);
    float avg_min = qbf(sum_min / (float)NCH);
    float total   = qbf(st);
    float avg     = qbf(total / (float)NTOT);
    // scale_fix in fp64 like numpy, then fp32 arithmetic like jnp
    const float scale_fix = (float)(1.0 / sqrt(2.0 * log((double)CHUNK_SZ)));
    float scale = qbf(1.0f / ((avg_max - avg_min) * scale_fix + 1e-5f));
    g_avg[c]   = avg;
    g_scale[c] = scale;
}

// ---------------------------------------------------------------------------
// Kernel 3: elementwise apply.  out = q(q((q(x)-avg)*scale)*q(gamma)+beta)
// one float4 per thread; 25088 blocks x 256 threads
// ---------------------------------------------------------------------------
__global__ __launch_bounds__(256) void rbn_apply(const float* __restrict__ x,
                                                 const float* __restrict__ gamma,
                                                 const float* __restrict__ beta,
                                                 float* __restrict__ out) {
    const size_t idx = (size_t)blockIdx.x * 256 + threadIdx.x; // float4 index
    if (idx >= TOTAL4) return;
    const int c = (int)((idx / HW4) % CC);

    const float avg   = g_avg[c];
    const float scale = g_scale[c];
    const float g     = qbf(__ldg(gamma + c));
    const float bt    = __ldg(beta + c);   // beta is NOT quantized in reference

    float4 v = __ldg(reinterpret_cast<const float4*>(x) + idx);
    float4 o;
    o.x = qbf(qbf((qbf(v.x) - avg) * scale) * g + bt);
    o.y = qbf(qbf((qbf(v.y) - avg) * scale) * g + bt);
    o.z = qbf(qbf((qbf(v.z) - avg) * scale) * g + bt);
    o.w = qbf(qbf((qbf(v.w) - avg) * scale) * g + bt);
    reinterpret_cast<float4*>(out)[idx] = o;
}

// ---------------------------------------------------------------------------
extern "C" void kernel_launch(void* const* d_in, const int* in_sizes, int n_in,
                              void* d_out, int out_size) {
    const float* x     = (const float*)d_in[0];
    const float* gamma = (const float*)d_in[1];
    const float* beta  = (const float*)d_in[2];
    float* out = (float*)d_out;

    rbn_reduce<<<CC * NCH, 256>>>(x);
    rbn_combine<<<1, 128>>>();
    rbn_apply<<<(unsigned)(TOTAL4 / 256), 256>>>(x, gamma, beta, out);
}

// round 2
// speedup vs baseline: 1.0335x; 1.0335x over previous
#include <cuda_runtime.h>
#include <cuda_bf16.h>
#include <math_constants.h>

// Problem constants (shapes fixed by the dataset)
#define CC      128      // channels
#define BATCH   64
#define HW      3136     // 56*56
#define NCH     8        // num_chunks
#define CHUNK_B (BATCH / NCH)       // 8 batches per chunk
#define CHUNK_SZ (CHUNK_B * HW)     // 25088 elements per chunk
#define NTOT    ((size_t)BATCH * HW)            // 200704
#define TOTAL4  ((size_t)BATCH * CC * HW / 4)   // 6,422,528 float4s
#define HW4     (HW / 4)            // 784 float4 per image-plane
#define PLANE_STRIDE ((size_t)CC * HW)          // floats between consecutive b, same c

// Scratch (no cudaMalloc allowed)
__device__ float g_cmax[CC * NCH];
__device__ float g_cmin[CC * NCH];
__device__ float g_csum[CC * NCH];
__device__ float g_avg[CC];
__device__ float g_scale[CC];

__device__ __forceinline__ float qbf(float v) {
    return __bfloat162float(__float2bfloat16(v));
}

// ---------------------------------------------------------------------------
// Kernel 1: per (channel, chunk) max / min / sum of bf16-quantized x.
// grid = CC*NCH = 1024 blocks, 256 threads.
// Loop order: outer over within-plane offset, inner UNROLLED over the 8 planes
// of the chunk -> 8 independent LDG.128 issued back-to-back (MLP = 8).
// ---------------------------------------------------------------------------
__global__ __launch_bounds__(256) void rbn_reduce(const float* __restrict__ x) {
    const int c = blockIdx.x >> 3;     // channel
    const int k = blockIdx.x & 7;      // chunk
    const int tid = threadIdx.x;

    const float* base = x + ((size_t)(k * CHUNK_B) * CC + c) * HW;

    float vmax = -CUDART_INF_F;
    float vmin =  CUDART_INF_F;
    float vsum = 0.0f;

    for (int i = tid; i < HW4; i += 256) {
        float4 v[CHUNK_B];
        #pragma unroll
        for (int b = 0; b < CHUNK_B; ++b) {
            v[b] = __ldg(reinterpret_cast<const float4*>(base + (size_t)b * PLANE_STRIDE) + i);
        }
        #pragma unroll
        for (int b = 0; b < CHUNK_B; ++b) {
            float a0 = qbf(v[b].x), a1 = qbf(v[b].y), a2 = qbf(v[b].z), a3 = qbf(v[b].w);
            vmax = fmaxf(vmax, fmaxf(fmaxf(a0, a1), fmaxf(a2, a3)));
            vmin = fminf(vmin, fminf(fminf(a0, a1), fminf(a2, a3)));
            vsum += (a0 + a1) + (a2 + a3);
        }
    }

    // block reduce: 8 warps
    __shared__ float smax[8], smin[8], ssum[8];
    const int lane = tid & 31, wid = tid >> 5;
    #pragma unroll
    for (int off = 16; off > 0; off >>= 1) {
        vmax = fmaxf(vmax, __shfl_xor_sync(0xffffffff, vmax, off));
        vmin = fminf(vmin, __shfl_xor_sync(0xffffffff, vmin, off));
        vsum += __shfl_xor_sync(0xffffffff, vsum, off);
    }
    if (lane == 0) { smax[wid] = vmax; smin[wid] = vmin; ssum[wid] = vsum; }
    __syncthreads();
    if (wid == 0) {
        vmax = (lane < 8) ? smax[lane] : -CUDART_INF_F;
        vmin = (lane < 8) ? smin[lane] :  CUDART_INF_F;
        vsum = (lane < 8) ? ssum[lane] : 0.0f;
        #pragma unroll
        for (int off = 4; off > 0; off >>= 1) {
            vmax = fmaxf(vmax, __shfl_xor_sync(0xffffffff, vmax, off));
            vmin = fminf(vmin, __shfl_xor_sync(0xffffffff, vmin, off));
            vsum += __shfl_xor_sync(0xffffffff, vsum, off);
        }
        if (lane == 0) {
            g_cmax[c * NCH + k] = vmax;
            g_cmin[c * NCH + k] = vmin;
            g_csum[c * NCH + k] = vsum;
        }
    }
}

// ---------------------------------------------------------------------------
// Kernel 2: per-channel combine, exactly following reference _q() chain.
// ---------------------------------------------------------------------------
__global__ void rbn_combine() {
    const int c = threadIdx.x;
    if (c >= CC) return;
    float sm = 0.f, sn = 0.f, st = 0.f;
    #pragma unroll
    for (int k = 0; k < NCH; ++k) {
        sm += g_cmax[c * NCH + k];
        sn += g_cmin[c * NCH + k];
        st += g_csum[c * NCH + k];
    }
    float sum_max = qbf(sm);
    float sum_min = qbf(sn);
    float avg_max = qbf(sum_max / (float)NCH);
    float avg_min = qbf(sum_min / (float)NCH);
    float total   = qbf(st);
    float avg     = qbf(total / (float)NTOT);
    const float scale_fix = (float)(1.0 / sqrt(2.0 * log((double)CHUNK_SZ)));
    float scale = qbf(1.0f / ((avg_max - avg_min) * scale_fix + 1e-5f));
    g_avg[c]   = avg;
    g_scale[c] = scale;
}

// ---------------------------------------------------------------------------
// Kernel 3: elementwise apply. out = q(q((q(x)-avg)*scale)*q(gamma)+beta)
// Each thread handles 4 CONSECUTIVE float4 (16 floats). Since HW4 = 784 is
// divisible by 4, a thread's segment never crosses a plane boundary -> one
// channel lookup per thread, 4 front-batched loads (MLP = 4).
// TOTAL4 / (256*4) = 6272 blocks exactly, no tail.
// ---------------------------------------------------------------------------
__global__ __launch_bounds__(256) void rbn_apply(const float* __restrict__ x,
                                                 const float* __restrict__ gamma,
                                                 const float* __restrict__ beta,
                                                 float* __restrict__ out) {
    const size_t idx4 = ((size_t)blockIdx.x * 256 + threadIdx.x) * 4; // first float4 index
    const int c = (int)((idx4 / HW4) % CC);

    const float avg   = g_avg[c];
    const float scale = g_scale[c];
    const float g     = qbf(__ldg(gamma + c));
    const float bt    = __ldg(beta + c);   // beta is NOT quantized in reference

    const float4* px = reinterpret_cast<const float4*>(x) + idx4;
    float4* po = reinterpret_cast<float4*>(out) + idx4;

    float4 v[4];
    #pragma unroll
    for (int j = 0; j < 4; ++j) v[j] = __ldg(px + j);

    #pragma unroll
    for (int j = 0; j < 4; ++j) {
        float4 o;
        o.x = qbf(qbf((qbf(v[j].x) - avg) * scale) * g + bt);
        o.y = qbf(qbf((qbf(v[j].y) - avg) * scale) * g + bt);
        o.z = qbf(qbf((qbf(v[j].z) - avg) * scale) * g + bt);
        o.w = qbf(qbf((qbf(v[j].w) - avg) * scale) * g + bt);
        po[j] = o;
    }
}

// ---------------------------------------------------------------------------
extern "C" void kernel_launch(void* const* d_in, const int* in_sizes, int n_in,
                              void* d_out, int out_size) {
    const float* x     = (const float*)d_in[0];
    const float* gamma = (const float*)d_in[1];
    const float* beta  = (const float*)d_in[2];
    float* out = (float*)d_out;

    rbn_reduce<<<CC * NCH, 256>>>(x);
    rbn_combine<<<1, 128>>>();
    rbn_apply<<<(unsigned)(TOTAL4 / 1024), 256>>>(x, gamma, beta, out);
}

// round 4
// speedup vs baseline: 1.2527x; 1.2121x over previous
#include <cuda_runtime.h>
#include <cuda_bf16.h>
#include <math_constants.h>

#define CC      128
#define BATCH   64
#define HW      3136
#define NCH     8
#define CHUNK_B (BATCH / NCH)            // 8
#define CHUNK_SZ (CHUNK_B * HW)          // 25088
#define NTOT    ((size_t)BATCH * HW)     // 200704
#define HW4     (HW / 4)                 // 784
#define PLANE_STRIDE ((size_t)CC * HW)   // floats between same-c consecutive b

__device__ float g_cmax[CC * NCH];
__device__ float g_cmin[CC * NCH];
__device__ float g_csum[CC * NCH];
__device__ float g_avg[CC];
__device__ float g_scale[CC];
__device__ unsigned int g_ctr = 0;

__device__ __forceinline__ float qbf(float v) {
    return __bfloat162float(__float2bfloat16(v));
}

// Quantize a pair of floats to bf16 (one CVT) and expand back to fp32 via
// bit ops (bf16 bits << 16 == fp32 bits).
__device__ __forceinline__ float2 q2(float a, float b) {
    __nv_bfloat162 p = __float22bfloat162_rn(make_float2(a, b));
    unsigned int u = *reinterpret_cast<unsigned int*>(&p);
    return make_float2(__uint_as_float(u << 16), __uint_as_float(u & 0xffff0000u));
}

// ---------------------------------------------------------------------------
// Kernel 1: per (channel, chunk) stats + fused per-channel combine in the
// last-finishing block.
//   max/min: computed on RAW values (bf16 rounding is monotone -> quantize
//            once at the end), sum: per-element quantized via paired CVT.
// grid = 1024 blocks (c*8+k), 256 threads.
// ---------------------------------------------------------------------------
__global__ __launch_bounds__(256) void rbn_reduce(const float* __restrict__ x) {
    const int c = blockIdx.x >> 3;
    const int k = blockIdx.x & 7;
    const int tid = threadIdx.x;

    const float* base = x + ((size_t)(k * CHUNK_B) * CC + c) * HW;

    float vmax = -CUDART_INF_F;
    float vmin =  CUDART_INF_F;
    float vsum = 0.0f;

    for (int i = tid; i < HW4; i += 256) {
        float4 v[CHUNK_B];
        #pragma unroll
        for (int b = 0; b < CHUNK_B; ++b)
            v[b] = __ldg(reinterpret_cast<const float4*>(base + (size_t)b * PLANE_STRIDE) + i);
        #pragma unroll
        for (int b = 0; b < CHUNK_B; ++b) {
            vmax = fmaxf(vmax, fmaxf(fmaxf(v[b].x, v[b].y), fmaxf(v[b].z, v[b].w)));
            vmin = fminf(vmin, fminf(fminf(v[b].x, v[b].y), fminf(v[b].z, v[b].w)));
            float2 p0 = q2(v[b].x, v[b].y);
            float2 p1 = q2(v[b].z, v[b].w);
            vsum += (p0.x + p0.y) + (p1.x + p1.y);
        }
    }

    __shared__ float smax[8], smin[8], ssum[8];
    __shared__ int s_last;
    const int lane = tid & 31, wid = tid >> 5;
    #pragma unroll
    for (int off = 16; off > 0; off >>= 1) {
        vmax = fmaxf(vmax, __shfl_xor_sync(0xffffffff, vmax, off));
        vmin = fminf(vmin, __shfl_xor_sync(0xffffffff, vmin, off));
        vsum += __shfl_xor_sync(0xffffffff, vsum, off);
    }
    if (lane == 0) { smax[wid] = vmax; smin[wid] = vmin; ssum[wid] = vsum; }
    __syncthreads();
    if (tid == 0) {
        vmax = smax[0]; vmin = smin[0]; vsum = ssum[0];
        #pragma unroll
        for (int w = 1; w < 8; ++w) {
            vmax = fmaxf(vmax, smax[w]);
            vmin = fminf(vmin, smin[w]);
            vsum += ssum[w];
        }
        g_cmax[c * NCH + k] = qbf(vmax);   // quantize once (monotone rounding)
        g_cmin[c * NCH + k] = qbf(vmin);
        g_csum[c * NCH + k] = vsum;
        __threadfence();
        unsigned int old = atomicAdd(&g_ctr, 1u);
        s_last = (old == (unsigned)(CC * NCH - 1));
    }
    __syncthreads();

    if (s_last) {
        // Fused combine: 128 threads, one channel each, exact _q() chain.
        if (tid < CC) {
            const int ch = tid;
            float sm = 0.f, sn = 0.f, st = 0.f;
            #pragma unroll
            for (int kk = 0; kk < NCH; ++kk) {
                sm += g_cmax[ch * NCH + kk];
                sn += g_cmin[ch * NCH + kk];
                st += g_csum[ch * NCH + kk];
            }
            float sum_max = qbf(sm);
            float sum_min = qbf(sn);
            float avg_max = qbf(sum_max / (float)NCH);
            float avg_min = qbf(sum_min / (float)NCH);
            float total   = qbf(st);
            float avg     = qbf(total / (float)NTOT);
            const float scale_fix = (float)(1.0 / sqrt(2.0 * log((double)CHUNK_SZ)));
            float scale = qbf(1.0f / ((avg_max - avg_min) * scale_fix + 1e-5f));
            g_avg[ch]   = avg;
            g_scale[ch] = scale;
        }
        __syncthreads();
        if (tid == 0) g_ctr = 0;   // reset for next graph replay
    }
}

// ---------------------------------------------------------------------------
// Kernel 2: apply. out = q(q((q(x)-avg)*scale)*q(gamma)+beta)
// One (b,c) plane per block: grid = 8192, 256 threads. x read should hit L2
// (x fits in 126MB L2 after reduce streamed it); output stored with __stcs
// (evict-first) so it does NOT evict x from L2.
// ---------------------------------------------------------------------------
__global__ __launch_bounds__(256) void rbn_apply(const float* __restrict__ x,
                                                 const float* __restrict__ gamma,
                                                 const float* __restrict__ beta,
                                                 float* __restrict__ out) {
    const int tid = threadIdx.x;
    const int c = blockIdx.x & (CC - 1);
    const size_t plane4 = (size_t)blockIdx.x * HW4;
    const float4* px = reinterpret_cast<const float4*>(x) + plane4;
    float4* po = reinterpret_cast<float4*>(out) + plane4;

    const float avg   = g_avg[c];
    const float scale = g_scale[c];
    const float g     = qbf(__ldg(gamma + c));
    const float bt    = __ldg(beta + c);   // beta NOT quantized in reference

    // 784 = 3*256 + 16 : three full iterations + 16-thread tail, front-batched.
    float4 v[3];
    v[0] = __ldg(px + tid);
    v[1] = __ldg(px + tid + 256);
    v[2] = __ldg(px + tid + 512);
    const bool tail = (tid < 16);
    float4 vt;
    if (tail) vt = __ldg(px + tid + 768);

    #pragma unroll
    for (int j = 0; j < 3; ++j) {
        float2 qa = q2(v[j].x, v[j].y);
        float2 qb = q2(v[j].z, v[j].w);
        float2 ta = q2((qa.x - avg) * scale, (qa.y - avg) * scale);
        float2 tb = q2((qb.x - avg) * scale, (qb.y - avg) * scale);
        float2 oa = q2(ta.x * g + bt, ta.y * g + bt);
        float2 ob = q2(tb.x * g + bt, tb.y * g + bt);
        float4 o = make_float4(oa.x, oa.y, ob.x, ob.y);
        __stcs(po + tid + j * 256, o);
    }
    if (tail) {
        float2 qa = q2(vt.x, vt.y);
        float2 qb = q2(vt.z, vt.w);
        float2 ta = q2((qa.x - avg) * scale, (qa.y - avg) * scale);
        float2 tb = q2((qb.x - avg) * scale, (qb.y - avg) * scale);
        float2 oa = q2(ta.x * g + bt, ta.y * g + bt);
        float2 ob = q2(tb.x * g + bt, tb.y * g + bt);
        __stcs(po + tid + 768, make_float4(oa.x, oa.y, ob.x, ob.y));
    }
}

// ---------------------------------------------------------------------------
extern "C" void kernel_launch(void* const* d_in, const int* in_sizes, int n_in,
                              void* d_out, int out_size) {
    const float* x     = (const float*)d_in[0];
    const float* gamma = (const float*)d_in[1];
    const float* beta  = (const float*)d_in[2];
    float* out = (float*)d_out;

    rbn_reduce<<<CC * NCH, 256>>>(x);
    rbn_apply<<<BATCH * CC, 256>>>(x, gamma, beta, out);
}